// round 1
// baseline (speedup 1.0000x reference)
#include <cuda_runtime.h>
#include <cuda_bf16.h>
#include <cstdio>

// Problem dims
#define BB 32
#define SS 64
#define TT 48
#define TM 47      // T-1 decoder steps
#define VV 32000
#define EE 512
#define HH 1024
#define H3 3072
#define H2 2048

// ---------------- scratch (device global, no allocs) ----------------
// offsets in floats
#define OFF_EMBS   0ull                                  // B*S*E      = 1048576
#define OFF_GI0    (OFF_EMBS   + (size_t)BB*SS*EE)       // B*S*3H     = 6291456
#define OFF_H0SEQ  (OFF_GI0    + (size_t)BB*SS*H3)       // B*S*H
#define OFF_GI1    (OFF_H0SEQ  + (size_t)BB*SS*HH)       // B*S*3H
#define OFF_ENCOUT (OFF_GI1    + (size_t)BB*SS*H3)       // B*S*H
#define OFF_PROJ   (OFF_ENCOUT + (size_t)BB*SS*HH)       // B*S*H
#define OFF_EMBT   (OFF_PROJ   + (size_t)BB*SS*HH)       // TM*B*E
#define OFF_EPRE   (OFF_EMBT   + (size_t)TM*BB*EE)       // TM*B*3H
#define OFF_H0     (OFF_EPRE   + (size_t)TM*BB*H3)       // B*H
#define OFF_H1     (OFF_H0     + (size_t)BB*HH)          // B*H
#define OFF_GH     (OFF_H1     + (size_t)BB*HH)          // B*3H
#define OFF_GI     (OFF_GH     + (size_t)BB*H3)          // B*3H
#define OFF_CTX    (OFF_GI     + (size_t)BB*H3)          // B*H
#define OFF_CAT    (OFF_CTX    + (size_t)BB*HH)          // TM*B*2H
#define SCRATCH_TOTAL (OFF_CAT + (size_t)TM*BB*H2)

__device__ float g_scratch[SCRATCH_TOTAL];

// ---------------- small helpers ----------------
__global__ void zero_kernel(float* p, int n) {
    int i = blockIdx.x * blockDim.x + threadIdx.x;
    if (i < n) p[i] = 0.f;
}

// encoder embedding: out[b][s][e] = table[ids[b*S+s]*E + e]
__global__ void embed_enc_kernel(const int* __restrict__ ids,
                                 const float* __restrict__ table,
                                 float* __restrict__ out) {
    int i = blockIdx.x * blockDim.x + threadIdx.x;
    if (i >= BB * SS * EE) return;
    int tok = i / EE;
    int e = i % EE;
    out[i] = table[(size_t)ids[tok] * EE + e];
}

// decoder embedding (time-major rows m = t*B + b): out[m][e] = table[tgt[b*T + t]*E + e]
__global__ void embed_dec_kernel(const int* __restrict__ tgt,
                                 const float* __restrict__ table,
                                 float* __restrict__ out) {
    int i = blockIdx.x * blockDim.x + threadIdx.x;
    if (i >= TM * BB * EE) return;
    int m = i / EE;
    int e = i % EE;
    int t = m / BB;
    int b = m % BB;
    out[i] = table[(size_t)tgt[b * TT + t] * EE + e];
}

// ---------------- big tiled GEMM: C[m,n] = sum_k A[m,k]*W[n,k] + bias[n] ----------------
// BM=BN=128, BK=16, 256 threads, 8x8 per thread. N must be multiple of 128. M guarded.
// PERM: remap output row m=t*B+b -> row b*TM + t (for writing logits directly).
template <bool PERM>
__global__ void __launch_bounds__(256)
gemm128_kernel(const float* __restrict__ A, int lda,
               const float* __restrict__ W, int ldw,
               const float* __restrict__ bias,
               float* __restrict__ C,
               int M, int N, int K) {
    __shared__ float As[16][128];
    __shared__ float Ws[16][128];
    const int bm = blockIdx.y * 128;
    const int bn = blockIdx.x * 128;
    const int tid = threadIdx.x;
    const int tm = (tid / 16) * 8;
    const int tn = (tid % 16) * 8;

    float acc[8][8];
#pragma unroll
    for (int i = 0; i < 8; i++)
#pragma unroll
        for (int j = 0; j < 8; j++) acc[i][j] = 0.f;

    for (int k0 = 0; k0 < K; k0 += 16) {
        // load A tile (128 x 16) : each thread 2x float4
#pragma unroll
        for (int j = 0; j < 2; j++) {
            int s = tid * 2 + j;          // 0..511
            int m = s >> 2;               // 0..127
            int kq = (s & 3) * 4;         // 0,4,8,12
            float4 v = make_float4(0.f, 0.f, 0.f, 0.f);
            if (bm + m < M)
                v = *reinterpret_cast<const float4*>(A + (size_t)(bm + m) * lda + k0 + kq);
            As[kq + 0][m] = v.x; As[kq + 1][m] = v.y;
            As[kq + 2][m] = v.z; As[kq + 3][m] = v.w;
        }
        // load W tile (128 x 16)
#pragma unroll
        for (int j = 0; j < 2; j++) {
            int s = tid * 2 + j;
            int n = s >> 2;
            int kq = (s & 3) * 4;
            float4 v = *reinterpret_cast<const float4*>(W + (size_t)(bn + n) * ldw + k0 + kq);
            Ws[kq + 0][n] = v.x; Ws[kq + 1][n] = v.y;
            Ws[kq + 2][n] = v.z; Ws[kq + 3][n] = v.w;
        }
        __syncthreads();
#pragma unroll
        for (int k = 0; k < 16; k++) {
            float a[8], b[8];
            float4 a0 = *reinterpret_cast<const float4*>(&As[k][tm]);
            float4 a1 = *reinterpret_cast<const float4*>(&As[k][tm + 4]);
            float4 b0 = *reinterpret_cast<const float4*>(&Ws[k][tn]);
            float4 b1 = *reinterpret_cast<const float4*>(&Ws[k][tn + 4]);
            a[0] = a0.x; a[1] = a0.y; a[2] = a0.z; a[3] = a0.w;
            a[4] = a1.x; a[5] = a1.y; a[6] = a1.z; a[7] = a1.w;
            b[0] = b0.x; b[1] = b0.y; b[2] = b0.z; b[3] = b0.w;
            b[4] = b1.x; b[5] = b1.y; b[6] = b1.z; b[7] = b1.w;
#pragma unroll
            for (int i = 0; i < 8; i++)
#pragma unroll
                for (int jj = 0; jj < 8; jj++)
                    acc[i][jj] += a[i] * b[jj];
        }
        __syncthreads();
    }

#pragma unroll
    for (int i = 0; i < 8; i++) {
        int m = bm + tm + i;
        if (m >= M) continue;
        size_t orow;
        if (PERM) {
            int b = m % BB;
            int t = m / BB;
            orow = (size_t)b * TM + t;
        } else {
            orow = (size_t)m;
        }
        float* cr = C + orow * N + bn + tn;
#pragma unroll
        for (int jj = 0; jj < 8; jj++) {
            int n = bn + tn + jj;
            float bb = bias ? bias[n] : 0.f;
            cr[jj] = acc[i][jj] + bb;
        }
    }
}

// ---------------- small-M GEMM (M == 32): C = [Cinit +] A@W^T [+ bias] ----------------
// grid.x = N/64, 256 threads. BK=32.
__global__ void __launch_bounds__(256)
gemm_small_kernel(const float* __restrict__ A, int lda,
                  const float* __restrict__ W, int ldw,
                  const float* __restrict__ bias,
                  const float* __restrict__ Cinit,  // may alias C; row stride N
                  float* __restrict__ C,
                  int N, int K) {
    __shared__ float As[32][33];
    __shared__ float Ws[64][33];
    const int tid = threadIdx.x;
    const int n_local = tid & 63;
    const int m0 = tid >> 6;  // 0..3
    const int bn = blockIdx.x * 64;

    float acc[8];
#pragma unroll
    for (int j = 0; j < 8; j++) acc[j] = 0.f;

    for (int k0 = 0; k0 < K; k0 += 32) {
        // A tile 32x32: one float4 per thread
        {
            int m = tid >> 3;            // 0..31
            int kq = (tid & 7) * 4;      // 0..28
            float4 v = *reinterpret_cast<const float4*>(A + (size_t)m * lda + k0 + kq);
            As[m][kq + 0] = v.x; As[m][kq + 1] = v.y;
            As[m][kq + 2] = v.z; As[m][kq + 3] = v.w;
        }
        // W tile 64x32: two float4 per thread
#pragma unroll
        for (int j = 0; j < 2; j++) {
            int s = tid * 2 + j;         // 0..511
            int n = s >> 3;              // 0..63
            int kq = (s & 7) * 4;
            float4 v = *reinterpret_cast<const float4*>(W + (size_t)(bn + n) * ldw + k0 + kq);
            Ws[n][kq + 0] = v.x; Ws[n][kq + 1] = v.y;
            Ws[n][kq + 2] = v.z; Ws[n][kq + 3] = v.w;
        }
        __syncthreads();
#pragma unroll 8
        for (int k = 0; k < 32; k++) {
            float wv = Ws[n_local][k];
#pragma unroll
            for (int j = 0; j < 8; j++)
                acc[j] += As[m0 + j * 4][k] * wv;
        }
        __syncthreads();
    }

    int n = bn + n_local;
    float bb = bias ? bias[n] : 0.f;
#pragma unroll
    for (int j = 0; j < 8; j++) {
        int m = m0 + j * 4;
        float init = Cinit ? Cinit[(size_t)m * N + n] : 0.f;
        C[(size_t)m * N + n] = init + acc[j] + bb;
    }
}

// ---------------- GRU gate ----------------
// gi row for batch b at gi + b*gi_stride (layout [r|z|n] of length 3H)
// gh is (B,3H) contiguous. h_in/h_out (B,H). Optional seq_out[b*seq_stride + h].
__global__ void gru_gate_kernel(const float* __restrict__ gi, int gi_stride,
                                const float* __restrict__ gh,
                                const float* __restrict__ h_in,
                                float* __restrict__ h_out,
                                float* __restrict__ seq_out, int seq_stride) {
    int idx = blockIdx.x * blockDim.x + threadIdx.x;
    if (idx >= BB * HH) return;
    int b = idx / HH;
    int h = idx % HH;
    const float* gib = gi + (size_t)b * gi_stride;
    const float* ghb = gh + (size_t)b * H3;
    float r = 1.f / (1.f + expf(-(gib[h] + ghb[h])));
    float z = 1.f / (1.f + expf(-(gib[HH + h] + ghb[HH + h])));
    float n = tanhf(gib[2 * HH + h] + r * ghb[2 * HH + h]);
    float hv = h_in[(size_t)b * HH + h];
    float out = (1.f - z) * n + z * hv;
    h_out[(size_t)b * HH + h] = out;
    if (seq_out) seq_out[(size_t)b * seq_stride + h] = out;
}

// ---------------- attention (one block per batch b) ----------------
// score = proj[b,s,:] . d1[b,:] masked; softmax; ctx = attn @ enc_out[b]
// writes ctx (B,H) and cat row (t*B+b) offset H.
__global__ void __launch_bounds__(256)
attn_kernel(const float* __restrict__ proj,
            const float* __restrict__ encout,
            const float* __restrict__ d1,
            const int* __restrict__ src_ids,
            float* __restrict__ ctx,
            float* __restrict__ catrow /* g_cat + t*B*2H */) {
    int b = blockIdx.x;
    __shared__ float sc[SS];
    int tid = threadIdx.x;
    int lane = tid & 31;
    int warp = tid >> 5;  // 8 warps
    const float* d1b = d1 + (size_t)b * HH;

    for (int s = warp; s < SS; s += 8) {
        const float* pr = proj + ((size_t)b * SS + s) * HH;
        float p = 0.f;
        for (int k = lane; k < HH; k += 32) p += pr[k] * d1b[k];
#pragma unroll
        for (int o = 16; o; o >>= 1) p += __shfl_xor_sync(0xffffffffu, p, o);
        if (lane == 0) sc[s] = (src_ids[b * SS + s] != 0) ? p : -1e9f;
    }
    __syncthreads();
    if (warp == 0) {
        float v0 = sc[lane], v1 = sc[lane + 32];
        float m = fmaxf(v0, v1);
#pragma unroll
        for (int o = 16; o; o >>= 1) m = fmaxf(m, __shfl_xor_sync(0xffffffffu, m, o));
        float e0 = expf(v0 - m), e1 = expf(v1 - m);
        float su = e0 + e1;
#pragma unroll
        for (int o = 16; o; o >>= 1) su += __shfl_xor_sync(0xffffffffu, su, o);
        sc[lane] = e0 / su;
        sc[lane + 32] = e1 / su;
    }
    __syncthreads();
    for (int h = tid; h < HH; h += 256) {
        const float* eb = encout + (size_t)b * SS * HH + h;
        float a = 0.f;
#pragma unroll 8
        for (int s = 0; s < SS; s++) a += sc[s] * eb[(size_t)s * HH];
        ctx[(size_t)b * HH + h] = a;
        catrow[(size_t)b * H2 + HH + h] = a;
    }
}

// ---------------- host launcher ----------------
extern "C" void kernel_launch(void* const* d_in, const int* in_sizes, int n_in,
                              void* d_out, int out_size) {
    const int*   src_ids  = (const int*)d_in[0];
    // d_in[1] = src_lens (all full, unused)
    const int*   tgt_ids  = (const int*)d_in[2];
    const float* enc_emb  = (const float*)d_in[3];
    const float* dec_emb  = (const float*)d_in[4];
    const float* enc_wih0 = (const float*)d_in[5];
    const float* enc_whh0 = (const float*)d_in[6];
    const float* enc_bih0 = (const float*)d_in[7];
    const float* enc_bhh0 = (const float*)d_in[8];
    const float* enc_wih1 = (const float*)d_in[9];
    const float* enc_whh1 = (const float*)d_in[10];
    const float* enc_bih1 = (const float*)d_in[11];
    const float* enc_bhh1 = (const float*)d_in[12];
    const float* dec_wih0 = (const float*)d_in[13];
    const float* dec_whh0 = (const float*)d_in[14];
    const float* dec_bih0 = (const float*)d_in[15];
    const float* dec_bhh0 = (const float*)d_in[16];
    const float* dec_wih1 = (const float*)d_in[17];
    const float* dec_whh1 = (const float*)d_in[18];
    const float* dec_bih1 = (const float*)d_in[19];
    const float* dec_bhh1 = (const float*)d_in[20];
    const float* attn_w   = (const float*)d_in[21];
    const float* out_w    = (const float*)d_in[22];
    const float* out_b    = (const float*)d_in[23];
    float* out = (float*)d_out;

    float* base = nullptr;
    cudaGetSymbolAddress((void**)&base, g_scratch);
    float* embS   = base + OFF_EMBS;
    float* gi0    = base + OFF_GI0;
    float* h0seq  = base + OFF_H0SEQ;
    float* gi1    = base + OFF_GI1;
    float* encout = base + OFF_ENCOUT;
    float* proj   = base + OFF_PROJ;
    float* embT   = base + OFF_EMBT;
    float* epre   = base + OFF_EPRE;
    float* h0     = base + OFF_H0;
    float* h1     = base + OFF_H1;
    float* gh     = base + OFF_GH;
    float* gi     = base + OFF_GI;
    float* ctx    = base + OFF_CTX;
    float* cat    = base + OFF_CAT;

    // ---- encoder ----
    embed_enc_kernel<<<(BB * SS * EE + 255) / 256, 256>>>(src_ids, enc_emb, embS);
    // gi0 = embS @ enc_wih0^T + bih0  (M=2048, N=3072, K=512)
    gemm128_kernel<false><<<dim3(H3 / 128, (BB * SS) / 128), 256>>>(
        embS, EE, enc_wih0, EE, enc_bih0, gi0, BB * SS, H3, EE);
    // h0 = h1 = 0
    zero_kernel<<<(2 * BB * HH + 255) / 256, 256>>>(h0, 2 * BB * HH);

    // layer-0 scan
    for (int t = 0; t < SS; t++) {
        gemm_small_kernel<<<H3 / 64, 256>>>(h0, HH, enc_whh0, HH, enc_bhh0, nullptr, gh, H3, HH);
        gru_gate_kernel<<<(BB * HH + 255) / 256, 256>>>(
            gi0 + (size_t)t * H3, SS * H3, gh, h0, h0, h0seq + (size_t)t * HH, SS * HH);
    }
    // gi1 = h0seq @ enc_wih1^T + bih1  (M=2048, N=3072, K=1024)
    gemm128_kernel<false><<<dim3(H3 / 128, (BB * SS) / 128), 256>>>(
        h0seq, HH, enc_wih1, HH, enc_bih1, gi1, BB * SS, H3, HH);
    // layer-1 scan
    for (int t = 0; t < SS; t++) {
        gemm_small_kernel<<<H3 / 64, 256>>>(h1, HH, enc_whh1, HH, enc_bhh1, nullptr, gh, H3, HH);
        gru_gate_kernel<<<(BB * HH + 255) / 256, 256>>>(
            gi1 + (size_t)t * H3, SS * H3, gh, h1, h1, encout + (size_t)t * HH, SS * HH);
    }
    // proj = encout @ attn_w^T  (M=2048, N=1024, K=1024)
    gemm128_kernel<false><<<dim3(HH / 128, (BB * SS) / 128), 256>>>(
        encout, HH, attn_w, HH, nullptr, proj, BB * SS, HH, HH);

    // ---- decoder pre ----
    embed_dec_kernel<<<(TM * BB * EE + 255) / 256, 256>>>(tgt_ids, dec_emb, embT);
    // epre = embT @ dec_wih0[:, :E]^T + dec_bih0  (M=1504, N=3072, K=512, ldw = E+H)
    gemm128_kernel<false><<<dim3(H3 / 128, (TM * BB + 127) / 128), 256>>>(
        embT, EE, dec_wih0, EE + HH, dec_bih0, epre, TM * BB, H3, EE);

    // ---- decoder loop (d0 = h0 buffer, d1 = h1 buffer: final encoder states) ----
    for (int t = 0; t < TM; t++) {
        float* epre_t = epre + (size_t)t * BB * H3;
        float* cat_t  = cat + (size_t)t * BB * H2;
        attn_kernel<<<BB, 256>>>(proj, encout, h1, src_ids, ctx, cat_t);
        // gi_layer0 = epre_t + ctx @ Wc^T   (Wc = dec_wih0[:, E:], ldw = E+H)
        gemm_small_kernel<<<H3 / 64, 256>>>(ctx, HH, dec_wih0 + EE, EE + HH, nullptr,
                                            epre_t, epre_t, H3, HH);
        // gh_layer0
        gemm_small_kernel<<<H3 / 64, 256>>>(h0, HH, dec_whh0, HH, dec_bhh0, nullptr, gh, H3, HH);
        gru_gate_kernel<<<(BB * HH + 255) / 256, 256>>>(epre_t, H3, gh, h0, h0, nullptr, 0);
        // layer 1
        gemm_small_kernel<<<H3 / 64, 256>>>(h0, HH, dec_wih1, HH, dec_bih1, nullptr, gi, H3, HH);
        gemm_small_kernel<<<H3 / 64, 256>>>(h1, HH, dec_whh1, HH, dec_bhh1, nullptr, gh, H3, HH);
        gru_gate_kernel<<<(BB * HH + 255) / 256, 256>>>(gi, H3, gh, h1, h1, cat_t, H2);
    }

    // ---- final projection: logits = cat @ out_w^T + out_b, permuted to (B, TM, V) ----
    gemm128_kernel<true><<<dim3(VV / 128, (TM * BB + 127) / 128), 256>>>(
        cat, H2, out_w, H2, out_b, out, TM * BB, VV, H2);
}

// round 2
// speedup vs baseline: 1.0065x; 1.0065x over previous
#include <cuda_runtime.h>
#include <cuda_bf16.h>
#include <cstdio>

// Problem dims
#define BB 32
#define SS 64
#define TT 48
#define TM 47      // T-1 decoder steps
#define VV 32000
#define EE 512
#define HH 1024
#define H3 3072
#define H2 2048

// ---------------- scratch (device global, no allocs) ----------------
// offsets in floats
#define OFF_EMBS   0ull                                  // B*S*E      = 1048576
#define OFF_GI0    (OFF_EMBS   + (size_t)BB*SS*EE)       // B*S*3H     = 6291456
#define OFF_H0SEQ  (OFF_GI0    + (size_t)BB*SS*H3)       // B*S*H
#define OFF_GI1    (OFF_H0SEQ  + (size_t)BB*SS*HH)       // B*S*3H
#define OFF_ENCOUT (OFF_GI1    + (size_t)BB*SS*H3)       // B*S*H
#define OFF_PROJ   (OFF_ENCOUT + (size_t)BB*SS*HH)       // B*S*H
#define OFF_EMBT   (OFF_PROJ   + (size_t)BB*SS*HH)       // TM*B*E
#define OFF_EPRE   (OFF_EMBT   + (size_t)TM*BB*EE)       // TM*B*3H
#define OFF_H0     (OFF_EPRE   + (size_t)TM*BB*H3)       // B*H
#define OFF_H1     (OFF_H0     + (size_t)BB*HH)          // B*H
#define OFF_GH     (OFF_H1     + (size_t)BB*HH)          // B*3H
#define OFF_GI     (OFF_GH     + (size_t)BB*H3)          // B*3H
#define OFF_CTX    (OFF_GI     + (size_t)BB*H3)          // B*H
#define OFF_CAT    (OFF_CTX    + (size_t)BB*HH)          // TM*B*2H
#define SCRATCH_TOTAL (OFF_CAT + (size_t)TM*BB*H2)

__device__ float g_scratch[SCRATCH_TOTAL];

// ---------------- small helpers ----------------
__global__ void zero_kernel(float* p, int n) {
    int i = blockIdx.x * blockDim.x + threadIdx.x;
    if (i < n) p[i] = 0.f;
}

// encoder embedding: out[b][s][e] = table[ids[b*S+s]*E + e]
__global__ void embed_enc_kernel(const int* __restrict__ ids,
                                 const float* __restrict__ table,
                                 float* __restrict__ out) {
    int i = blockIdx.x * blockDim.x + threadIdx.x;
    if (i >= BB * SS * EE) return;
    int tok = i / EE;
    int e = i % EE;
    out[i] = table[(size_t)ids[tok] * EE + e];
}

// decoder embedding (time-major rows m = t*B + b): out[m][e] = table[tgt[b*T + t]*E + e]
__global__ void embed_dec_kernel(const int* __restrict__ tgt,
                                 const float* __restrict__ table,
                                 float* __restrict__ out) {
    int i = blockIdx.x * blockDim.x + threadIdx.x;
    if (i >= TM * BB * EE) return;
    int m = i / EE;
    int e = i % EE;
    int t = m / BB;
    int b = m % BB;
    out[i] = table[(size_t)tgt[b * TT + t] * EE + e];
}

// ---------------- big tiled GEMM: C[m,n] = sum_k A[m,k]*W[n,k] + bias[n] ----------------
// BM=BN=128, BK=16, 256 threads, 8x8 per thread. N must be multiple of 128. M guarded.
// PERM: remap output row m=t*B+b -> row b*TM + t (for writing logits directly).
template <bool PERM>
__global__ void __launch_bounds__(256)
gemm128_kernel(const float* __restrict__ A, int lda,
               const float* __restrict__ W, int ldw,
               const float* __restrict__ bias,
               float* __restrict__ C,
               int M, int N, int K) {
    __shared__ float As[16][128];
    __shared__ float Ws[16][128];
    const int bm = blockIdx.y * 128;
    const int bn = blockIdx.x * 128;
    const int tid = threadIdx.x;
    const int tm = (tid / 16) * 8;
    const int tn = (tid % 16) * 8;

    float acc[8][8];
#pragma unroll
    for (int i = 0; i < 8; i++)
#pragma unroll
        for (int j = 0; j < 8; j++) acc[i][j] = 0.f;

    for (int k0 = 0; k0 < K; k0 += 16) {
        // load A tile (128 x 16) : each thread 2x float4
#pragma unroll
        for (int j = 0; j < 2; j++) {
            int s = tid * 2 + j;          // 0..511
            int m = s >> 2;               // 0..127
            int kq = (s & 3) * 4;         // 0,4,8,12
            float4 v = make_float4(0.f, 0.f, 0.f, 0.f);
            if (bm + m < M)
                v = *reinterpret_cast<const float4*>(A + (size_t)(bm + m) * lda + k0 + kq);
            As[kq + 0][m] = v.x; As[kq + 1][m] = v.y;
            As[kq + 2][m] = v.z; As[kq + 3][m] = v.w;
        }
        // load W tile (128 x 16)
#pragma unroll
        for (int j = 0; j < 2; j++) {
            int s = tid * 2 + j;
            int n = s >> 2;
            int kq = (s & 3) * 4;
            float4 v = *reinterpret_cast<const float4*>(W + (size_t)(bn + n) * ldw + k0 + kq);
            Ws[kq + 0][n] = v.x; Ws[kq + 1][n] = v.y;
            Ws[kq + 2][n] = v.z; Ws[kq + 3][n] = v.w;
        }
        __syncthreads();
#pragma unroll
        for (int k = 0; k < 16; k++) {
            float a[8], b[8];
            float4 a0 = *reinterpret_cast<const float4*>(&As[k][tm]);
            float4 a1 = *reinterpret_cast<const float4*>(&As[k][tm + 4]);
            float4 b0 = *reinterpret_cast<const float4*>(&Ws[k][tn]);
            float4 b1 = *reinterpret_cast<const float4*>(&Ws[k][tn + 4]);
            a[0] = a0.x; a[1] = a0.y; a[2] = a0.z; a[3] = a0.w;
            a[4] = a1.x; a[5] = a1.y; a[6] = a1.z; a[7] = a1.w;
            b[0] = b0.x; b[1] = b0.y; b[2] = b0.z; b[3] = b0.w;
            b[4] = b1.x; b[5] = b1.y; b[6] = b1.z; b[7] = b1.w;
#pragma unroll
            for (int i = 0; i < 8; i++)
#pragma unroll
                for (int jj = 0; jj < 8; jj++)
                    acc[i][jj] += a[i] * b[jj];
        }
        __syncthreads();
    }

#pragma unroll
    for (int i = 0; i < 8; i++) {
        int m = bm + tm + i;
        if (m >= M) continue;
        size_t orow;
        if (PERM) {
            int b = m % BB;
            int t = m / BB;
            orow = (size_t)b * TM + t;
        } else {
            orow = (size_t)m;
        }
        float* cr = C + orow * N + bn + tn;
#pragma unroll
        for (int jj = 0; jj < 8; jj++) {
            int n = bn + tn + jj;
            float bb = bias ? bias[n] : 0.f;
            cr[jj] = acc[i][jj] + bb;
        }
    }
}

// ---------------- small-M GEMM (M == 32): C = [Cinit +] A@W^T [+ bias] ----------------
// grid.x = N/64, 256 threads. BK=32.
__global__ void __launch_bounds__(256)
gemm_small_kernel(const float* __restrict__ A, int lda,
                  const float* __restrict__ W, int ldw,
                  const float* __restrict__ bias,
                  const float* __restrict__ Cinit,  // may alias C; row stride N
                  float* __restrict__ C,
                  int N, int K) {
    __shared__ float As[32][33];
    __shared__ float Ws[64][33];
    const int tid = threadIdx.x;
    const int n_local = tid & 63;
    const int m0 = tid >> 6;  // 0..3
    const int bn = blockIdx.x * 64;

    float acc[8];
#pragma unroll
    for (int j = 0; j < 8; j++) acc[j] = 0.f;

    for (int k0 = 0; k0 < K; k0 += 32) {
        // A tile 32x32: one float4 per thread
        {
            int m = tid >> 3;            // 0..31
            int kq = (tid & 7) * 4;      // 0..28
            float4 v = *reinterpret_cast<const float4*>(A + (size_t)m * lda + k0 + kq);
            As[m][kq + 0] = v.x; As[m][kq + 1] = v.y;
            As[m][kq + 2] = v.z; As[m][kq + 3] = v.w;
        }
        // W tile 64x32: two float4 per thread
#pragma unroll
        for (int j = 0; j < 2; j++) {
            int s = tid * 2 + j;         // 0..511
            int n = s >> 3;              // 0..63
            int kq = (s & 7) * 4;
            float4 v = *reinterpret_cast<const float4*>(W + (size_t)(bn + n) * ldw + k0 + kq);
            Ws[n][kq + 0] = v.x; Ws[n][kq + 1] = v.y;
            Ws[n][kq + 2] = v.z; Ws[n][kq + 3] = v.w;
        }
        __syncthreads();
#pragma unroll 8
        for (int k = 0; k < 32; k++) {
            float wv = Ws[n_local][k];
#pragma unroll
            for (int j = 0; j < 8; j++)
                acc[j] += As[m0 + j * 4][k] * wv;
        }
        __syncthreads();
    }

    int n = bn + n_local;
    float bb = bias ? bias[n] : 0.f;
#pragma unroll
    for (int j = 0; j < 8; j++) {
        int m = m0 + j * 4;
        float init = Cinit ? Cinit[(size_t)m * N + n] : 0.f;
        C[(size_t)m * N + n] = init + acc[j] + bb;
    }
}

// ---------------- GRU gate ----------------
// gi row for batch b at gi + b*gi_stride (layout [r|z|n] of length 3H)
// gh is (B,3H) contiguous. h_in/h_out (B,H). Optional seq_out[b*seq_stride + h].
__global__ void gru_gate_kernel(const float* __restrict__ gi, int gi_stride,
                                const float* __restrict__ gh,
                                const float* __restrict__ h_in,
                                float* __restrict__ h_out,
                                float* __restrict__ seq_out, int seq_stride) {
    int idx = blockIdx.x * blockDim.x + threadIdx.x;
    if (idx >= BB * HH) return;
    int b = idx / HH;
    int h = idx % HH;
    const float* gib = gi + (size_t)b * gi_stride;
    const float* ghb = gh + (size_t)b * H3;
    float r = 1.f / (1.f + expf(-(gib[h] + ghb[h])));
    float z = 1.f / (1.f + expf(-(gib[HH + h] + ghb[HH + h])));
    float n = tanhf(gib[2 * HH + h] + r * ghb[2 * HH + h]);
    float hv = h_in[(size_t)b * HH + h];
    float out = (1.f - z) * n + z * hv;
    h_out[(size_t)b * HH + h] = out;
    if (seq_out) seq_out[(size_t)b * seq_stride + h] = out;
}

// ---------------- attention (one block per batch b) ----------------
// score = proj[b,s,:] . d1[b,:] masked; softmax; ctx = attn @ enc_out[b]
// writes ctx (B,H) and cat row (t*B+b) offset H.
__global__ void __launch_bounds__(256)
attn_kernel(const float* __restrict__ proj,
            const float* __restrict__ encout,
            const float* __restrict__ d1,
            const int* __restrict__ src_ids,
            float* __restrict__ ctx,
            float* __restrict__ catrow /* g_cat + t*B*2H */) {
    int b = blockIdx.x;
    __shared__ float sc[SS];
    int tid = threadIdx.x;
    int lane = tid & 31;
    int warp = tid >> 5;  // 8 warps
    const float* d1b = d1 + (size_t)b * HH;

    for (int s = warp; s < SS; s += 8) {
        const float* pr = proj + ((size_t)b * SS + s) * HH;
        float p = 0.f;
        for (int k = lane; k < HH; k += 32) p += pr[k] * d1b[k];
#pragma unroll
        for (int o = 16; o; o >>= 1) p += __shfl_xor_sync(0xffffffffu, p, o);
        if (lane == 0) sc[s] = (src_ids[b * SS + s] != 0) ? p : -1e9f;
    }
    __syncthreads();
    if (warp == 0) {
        float v0 = sc[lane], v1 = sc[lane + 32];
        float m = fmaxf(v0, v1);
#pragma unroll
        for (int o = 16; o; o >>= 1) m = fmaxf(m, __shfl_xor_sync(0xffffffffu, m, o));
        float e0 = expf(v0 - m), e1 = expf(v1 - m);
        float su = e0 + e1;
#pragma unroll
        for (int o = 16; o; o >>= 1) su += __shfl_xor_sync(0xffffffffu, su, o);
        sc[lane] = e0 / su;
        sc[lane + 32] = e1 / su;
    }
    __syncthreads();
    for (int h = tid; h < HH; h += 256) {
        const float* eb = encout + (size_t)b * SS * HH + h;
        float a = 0.f;
#pragma unroll 8
        for (int s = 0; s < SS; s++) a += sc[s] * eb[(size_t)s * HH];
        ctx[(size_t)b * HH + h] = a;
        catrow[(size_t)b * H2 + HH + h] = a;
    }
}

// ---------------- host launcher ----------------
extern "C" void kernel_launch(void* const* d_in, const int* in_sizes, int n_in,
                              void* d_out, int out_size) {
    const int*   src_ids  = (const int*)d_in[0];
    // d_in[1] = src_lens (all full, unused)
    const int*   tgt_ids  = (const int*)d_in[2];
    const float* enc_emb  = (const float*)d_in[3];
    const float* dec_emb  = (const float*)d_in[4];
    const float* enc_wih0 = (const float*)d_in[5];
    const float* enc_whh0 = (const float*)d_in[6];
    const float* enc_bih0 = (const float*)d_in[7];
    const float* enc_bhh0 = (const float*)d_in[8];
    const float* enc_wih1 = (const float*)d_in[9];
    const float* enc_whh1 = (const float*)d_in[10];
    const float* enc_bih1 = (const float*)d_in[11];
    const float* enc_bhh1 = (const float*)d_in[12];
    const float* dec_wih0 = (const float*)d_in[13];
    const float* dec_whh0 = (const float*)d_in[14];
    const float* dec_bih0 = (const float*)d_in[15];
    const float* dec_bhh0 = (const float*)d_in[16];
    const float* dec_wih1 = (const float*)d_in[17];
    const float* dec_whh1 = (const float*)d_in[18];
    const float* dec_bih1 = (const float*)d_in[19];
    const float* dec_bhh1 = (const float*)d_in[20];
    const float* attn_w   = (const float*)d_in[21];
    const float* out_w    = (const float*)d_in[22];
    const float* out_b    = (const float*)d_in[23];
    float* out = (float*)d_out;

    float* base = nullptr;
    cudaGetSymbolAddress((void**)&base, g_scratch);
    float* embS   = base + OFF_EMBS;
    float* gi0    = base + OFF_GI0;
    float* h0seq  = base + OFF_H0SEQ;
    float* gi1    = base + OFF_GI1;
    float* encout = base + OFF_ENCOUT;
    float* proj   = base + OFF_PROJ;
    float* embT   = base + OFF_EMBT;
    float* epre   = base + OFF_EPRE;
    float* h0     = base + OFF_H0;
    float* h1     = base + OFF_H1;
    float* gh     = base + OFF_GH;
    float* gi     = base + OFF_GI;
    float* ctx    = base + OFF_CTX;
    float* cat    = base + OFF_CAT;

    // ---- encoder ----
    embed_enc_kernel<<<(BB * SS * EE + 255) / 256, 256>>>(src_ids, enc_emb, embS);
    // gi0 = embS @ enc_wih0^T + bih0  (M=2048, N=3072, K=512)
    gemm128_kernel<false><<<dim3(H3 / 128, (BB * SS) / 128), 256>>>(
        embS, EE, enc_wih0, EE, enc_bih0, gi0, BB * SS, H3, EE);
    // h0 = h1 = 0
    zero_kernel<<<(2 * BB * HH + 255) / 256, 256>>>(h0, 2 * BB * HH);

    // layer-0 scan
    for (int t = 0; t < SS; t++) {
        gemm_small_kernel<<<H3 / 64, 256>>>(h0, HH, enc_whh0, HH, enc_bhh0, nullptr, gh, H3, HH);
        gru_gate_kernel<<<(BB * HH + 255) / 256, 256>>>(
            gi0 + (size_t)t * H3, SS * H3, gh, h0, h0, h0seq + (size_t)t * HH, SS * HH);
    }
    // gi1 = h0seq @ enc_wih1^T + bih1  (M=2048, N=3072, K=1024)
    gemm128_kernel<false><<<dim3(H3 / 128, (BB * SS) / 128), 256>>>(
        h0seq, HH, enc_wih1, HH, enc_bih1, gi1, BB * SS, H3, HH);
    // layer-1 scan
    for (int t = 0; t < SS; t++) {
        gemm_small_kernel<<<H3 / 64, 256>>>(h1, HH, enc_whh1, HH, enc_bhh1, nullptr, gh, H3, HH);
        gru_gate_kernel<<<(BB * HH + 255) / 256, 256>>>(
            gi1 + (size_t)t * H3, SS * H3, gh, h1, h1, encout + (size_t)t * HH, SS * HH);
    }
    // proj = encout @ attn_w^T  (M=2048, N=1024, K=1024)
    gemm128_kernel<false><<<dim3(HH / 128, (BB * SS) / 128), 256>>>(
        encout, HH, attn_w, HH, nullptr, proj, BB * SS, HH, HH);

    // ---- decoder pre ----
    embed_dec_kernel<<<(TM * BB * EE + 255) / 256, 256>>>(tgt_ids, dec_emb, embT);
    // epre = embT @ dec_wih0[:, :E]^T + dec_bih0  (M=1504, N=3072, K=512, ldw = E+H)
    gemm128_kernel<false><<<dim3(H3 / 128, (TM * BB + 127) / 128), 256>>>(
        embT, EE, dec_wih0, EE + HH, dec_bih0, epre, TM * BB, H3, EE);

    // ---- decoder loop (d0 = h0 buffer, d1 = h1 buffer: final encoder states) ----
    for (int t = 0; t < TM; t++) {
        float* epre_t = epre + (size_t)t * BB * H3;
        float* cat_t  = cat + (size_t)t * BB * H2;
        attn_kernel<<<BB, 256>>>(proj, encout, h1, src_ids, ctx, cat_t);
        // gi_layer0 = epre_t + ctx @ Wc^T   (Wc = dec_wih0[:, E:], ldw = E+H)
        gemm_small_kernel<<<H3 / 64, 256>>>(ctx, HH, dec_wih0 + EE, EE + HH, nullptr,
                                            epre_t, epre_t, H3, HH);
        // gh_layer0
        gemm_small_kernel<<<H3 / 64, 256>>>(h0, HH, dec_whh0, HH, dec_bhh0, nullptr, gh, H3, HH);
        gru_gate_kernel<<<(BB * HH + 255) / 256, 256>>>(epre_t, H3, gh, h0, h0, nullptr, 0);
        // layer 1
        gemm_small_kernel<<<H3 / 64, 256>>>(h0, HH, dec_wih1, HH, dec_bih1, nullptr, gi, H3, HH);
        gemm_small_kernel<<<H3 / 64, 256>>>(h1, HH, dec_whh1, HH, dec_bhh1, nullptr, gh, H3, HH);
        gru_gate_kernel<<<(BB * HH + 255) / 256, 256>>>(gi, H3, gh, h1, h1, cat_t, H2);
    }

    // ---- final projection: logits = cat @ out_w^T + out_b, permuted to (B, TM, V) ----
    gemm128_kernel<true><<<dim3(VV / 128, (TM * BB + 127) / 128), 256>>>(
        cat, H2, out_w, H2, out_b, out, TM * BB, VV, H2);
}

// round 3
// speedup vs baseline: 1.1143x; 1.1071x over previous
#include <cuda_runtime.h>
#include <cuda_bf16.h>
#include <cstdio>

// Problem dims
#define BB 32
#define SS 64
#define TT 48
#define TM 47      // T-1 decoder steps
#define VV 32000
#define EE 512
#define HH 1024
#define H3 3072
#define H2 2048

// ---------------- scratch (device global, no allocs) ----------------
#define OFF_EMBS   0ull                                  // B*S*E
#define OFF_GI0    (OFF_EMBS   + (size_t)BB*SS*EE)       // B*S*3H
#define OFF_H0SEQ  (OFF_GI0    + (size_t)BB*SS*H3)       // B*S*H
#define OFF_GI1    (OFF_H0SEQ  + (size_t)BB*SS*HH)       // B*S*3H
#define OFF_ENCOUT (OFF_GI1    + (size_t)BB*SS*H3)       // B*S*H
#define OFF_PROJ   (OFF_ENCOUT + (size_t)BB*SS*HH)       // B*S*H
#define OFF_EMBT   (OFF_PROJ   + (size_t)BB*SS*HH)       // TM*B*E
#define OFF_EPRE   (OFF_EMBT   + (size_t)TM*BB*EE)       // TM*B*3H
#define OFF_CAT    (OFF_EPRE   + (size_t)TM*BB*H3)       // TM*B*2H
#define OFF_H0A    (OFF_CAT    + (size_t)TM*BB*H2)       // 32*1024 packed-transposed
#define OFF_H0B    (OFF_H0A    + (size_t)BB*HH)
#define OFF_H1A    (OFF_H0B    + (size_t)BB*HH)
#define OFF_H1B    (OFF_H1A    + (size_t)BB*HH)
#define OFF_CTXT   (OFF_H1B    + (size_t)BB*HH)
#define SCRATCH_TOTAL (OFF_CTXT + (size_t)BB*HH)

__device__ float g_scratch[SCRATCH_TOTAL];

// packed-transposed state layout: element (k, b) at (k>>2)*128 + b*4 + (k&3)
// -> a float4 at ptr + (k0>>2)*32*4 + b*4 holds k0..k0+3 for batch b (k0%4==0)
__device__ __forceinline__ size_t pt_idx(int k, int b) {
    return (size_t)((k >> 2) * 128 + b * 4 + (k & 3));
}

// ---------------- small helpers ----------------
__global__ void zero_kernel(float* p, int n) {
    int i = blockIdx.x * blockDim.x + threadIdx.x;
    if (i < n) p[i] = 0.f;
}

__global__ void embed_enc_kernel(const int* __restrict__ ids,
                                 const float* __restrict__ table,
                                 float* __restrict__ out) {
    int i = blockIdx.x * blockDim.x + threadIdx.x;
    if (i >= BB * SS * EE) return;
    int tok = i / EE;
    int e = i % EE;
    out[i] = table[(size_t)ids[tok] * EE + e];
}

// decoder embedding rows m = t*B + b
__global__ void embed_dec_kernel(const int* __restrict__ tgt,
                                 const float* __restrict__ table,
                                 float* __restrict__ out) {
    int i = blockIdx.x * blockDim.x + threadIdx.x;
    if (i >= TM * BB * EE) return;
    int m = i / EE;
    int e = i % EE;
    int t = m / BB;
    int b = m % BB;
    out[i] = table[(size_t)tgt[b * TT + t] * EE + e];
}

// ---------------- big tiled GEMM: C[m,n] = sum_k A[m,k]*W[n,k] + bias[n] ----------------
template <bool PERM>
__global__ void __launch_bounds__(256)
gemm128_kernel(const float* __restrict__ A, int lda,
               const float* __restrict__ W, int ldw,
               const float* __restrict__ bias,
               float* __restrict__ C,
               int M, int N, int K) {
    __shared__ float As[16][128];
    __shared__ float Ws[16][128];
    const int bm = blockIdx.y * 128;
    const int bn = blockIdx.x * 128;
    const int tid = threadIdx.x;
    const int tm = (tid / 16) * 8;
    const int tn = (tid % 16) * 8;

    float acc[8][8];
#pragma unroll
    for (int i = 0; i < 8; i++)
#pragma unroll
        for (int j = 0; j < 8; j++) acc[i][j] = 0.f;

    for (int k0 = 0; k0 < K; k0 += 16) {
#pragma unroll
        for (int j = 0; j < 2; j++) {
            int s = tid * 2 + j;
            int m = s >> 2;
            int kq = (s & 3) * 4;
            float4 v = make_float4(0.f, 0.f, 0.f, 0.f);
            if (bm + m < M)
                v = *reinterpret_cast<const float4*>(A + (size_t)(bm + m) * lda + k0 + kq);
            As[kq + 0][m] = v.x; As[kq + 1][m] = v.y;
            As[kq + 2][m] = v.z; As[kq + 3][m] = v.w;
        }
#pragma unroll
        for (int j = 0; j < 2; j++) {
            int s = tid * 2 + j;
            int n = s >> 2;
            int kq = (s & 3) * 4;
            float4 v = *reinterpret_cast<const float4*>(W + (size_t)(bn + n) * ldw + k0 + kq);
            Ws[kq + 0][n] = v.x; Ws[kq + 1][n] = v.y;
            Ws[kq + 2][n] = v.z; Ws[kq + 3][n] = v.w;
        }
        __syncthreads();
#pragma unroll
        for (int k = 0; k < 16; k++) {
            float a[8], b[8];
            float4 a0 = *reinterpret_cast<const float4*>(&As[k][tm]);
            float4 a1 = *reinterpret_cast<const float4*>(&As[k][tm + 4]);
            float4 b0 = *reinterpret_cast<const float4*>(&Ws[k][tn]);
            float4 b1 = *reinterpret_cast<const float4*>(&Ws[k][tn + 4]);
            a[0] = a0.x; a[1] = a0.y; a[2] = a0.z; a[3] = a0.w;
            a[4] = a1.x; a[5] = a1.y; a[6] = a1.z; a[7] = a1.w;
            b[0] = b0.x; b[1] = b0.y; b[2] = b0.z; b[3] = b0.w;
            b[4] = b1.x; b[5] = b1.y; b[6] = b1.z; b[7] = b1.w;
#pragma unroll
            for (int i = 0; i < 8; i++)
#pragma unroll
                for (int jj = 0; jj < 8; jj++)
                    acc[i][jj] += a[i] * b[jj];
        }
        __syncthreads();
    }

#pragma unroll
    for (int i = 0; i < 8; i++) {
        int m = bm + tm + i;
        if (m >= M) continue;
        size_t orow;
        if (PERM) {
            int b = m % BB;
            int t = m / BB;
            orow = (size_t)b * TM + t;
        } else {
            orow = (size_t)m;
        }
        float* cr = C + orow * N + bn + tn;
#pragma unroll
        for (int jj = 0; jj < 8; jj++) {
            int n = bn + tn + jj;
            float bb = bias ? bias[n] : 0.f;
            cr[jj] = acc[i][jj] + bb;
        }
    }
}

// ---------------- fused encoder GRU step ----------------
// warp = one hidden unit h (1024 warps), lane = batch b.
// gi precomputed (incl. bih): row for batch b at gi + b*gi_stride, cols [r|z|n].
// state in packed-transposed layout; ht4_in != ht4_out (ping-pong).
__global__ void __launch_bounds__(256)
gru_enc_step(const float* __restrict__ gi, int gi_stride,
             const float* __restrict__ whh,
             const float* __restrict__ bhh,
             const float* __restrict__ ht4_in,
             float* __restrict__ ht4_out,
             float* __restrict__ seq_out, int seq_stride) {
    const int h = blockIdx.x * 8 + (threadIdx.x >> 5);
    const int b = threadIdx.x & 31;
    const float* w0 = whh + (size_t)h * HH;
    const float* w1 = whh + (size_t)(HH + h) * HH;
    const float* w2 = whh + (size_t)(2 * HH + h) * HH;

    float ar = 0.f, az = 0.f, an = 0.f;
#pragma unroll 8
    for (int q = 0; q < HH / 4; q++) {
        float4 a  = *reinterpret_cast<const float4*>(ht4_in + (size_t)q * 128 + b * 4);
        float4 wr = *reinterpret_cast<const float4*>(w0 + q * 4);
        float4 wz = *reinterpret_cast<const float4*>(w1 + q * 4);
        float4 wn = *reinterpret_cast<const float4*>(w2 + q * 4);
        ar += a.x * wr.x + a.y * wr.y + a.z * wr.z + a.w * wr.w;
        az += a.x * wz.x + a.y * wz.y + a.z * wz.z + a.w * wz.w;
        an += a.x * wn.x + a.y * wn.y + a.z * wn.z + a.w * wn.w;
    }
    const float* gib = gi + (size_t)b * gi_stride;
    float hr = ar + bhh[h];
    float hz = az + bhh[HH + h];
    float hn = an + bhh[2 * HH + h];
    float r = 1.f / (1.f + expf(-(gib[h] + hr)));
    float z = 1.f / (1.f + expf(-(gib[HH + h] + hz)));
    float n = tanhf(gib[2 * HH + h] + r * hn);
    float hp = ht4_in[pt_idx(h, b)];
    float out = (1.f - z) * n + z * hp;
    ht4_out[pt_idx(h, b)] = out;
    seq_out[(size_t)b * seq_stride + h] = out;
}

// ---------------- fused decoder GRU step (2 GEMM phases + gate) ----------------
// i-side: gi_init (matrix epre rows and/or bias vector) + x @ wih[:, off:off+H]^T
// h-side: h @ whh^T + bhh
__global__ void __launch_bounds__(256)
gru_dec_step(const float* __restrict__ gi_mat, int gi_stride,   // nullable
             const float* __restrict__ gi_vec,                  // nullable (bih)
             const float* __restrict__ xt4,                     // packed-transposed x
             const float* __restrict__ wih, int wih_ld, int wih_off,
             const float* __restrict__ ht4_in,
             const float* __restrict__ whh,
             const float* __restrict__ bhh,
             float* __restrict__ ht4_out,
             float* __restrict__ cat_out)                       // nullable: + b*H2 + h
{
    const int h = blockIdx.x * 8 + (threadIdx.x >> 5);
    const int b = threadIdx.x & 31;

    // phase 1: h-side (whh)
    const float* w0 = whh + (size_t)h * HH;
    const float* w1 = whh + (size_t)(HH + h) * HH;
    const float* w2 = whh + (size_t)(2 * HH + h) * HH;
    float ar = 0.f, az = 0.f, anh = 0.f;
#pragma unroll 8
    for (int q = 0; q < HH / 4; q++) {
        float4 a  = *reinterpret_cast<const float4*>(ht4_in + (size_t)q * 128 + b * 4);
        float4 wr = *reinterpret_cast<const float4*>(w0 + q * 4);
        float4 wz = *reinterpret_cast<const float4*>(w1 + q * 4);
        float4 wn = *reinterpret_cast<const float4*>(w2 + q * 4);
        ar  += a.x * wr.x + a.y * wr.y + a.z * wr.z + a.w * wr.w;
        az  += a.x * wz.x + a.y * wz.y + a.z * wz.z + a.w * wz.w;
        anh += a.x * wn.x + a.y * wn.y + a.z * wn.z + a.w * wn.w;
    }
    // phase 2: x-side (wih sub-block)
    const float* v0 = wih + (size_t)h * wih_ld + wih_off;
    const float* v1 = wih + (size_t)(HH + h) * wih_ld + wih_off;
    const float* v2 = wih + (size_t)(2 * HH + h) * wih_ld + wih_off;
    float anx = 0.f;
#pragma unroll 8
    for (int q = 0; q < HH / 4; q++) {
        float4 a  = *reinterpret_cast<const float4*>(xt4 + (size_t)q * 128 + b * 4);
        float4 wr = *reinterpret_cast<const float4*>(v0 + q * 4);
        float4 wz = *reinterpret_cast<const float4*>(v1 + q * 4);
        float4 wn = *reinterpret_cast<const float4*>(v2 + q * 4);
        ar  += a.x * wr.x + a.y * wr.y + a.z * wr.z + a.w * wr.w;
        az  += a.x * wz.x + a.y * wz.y + a.z * wz.z + a.w * wz.w;
        anx += a.x * wn.x + a.y * wn.y + a.z * wn.z + a.w * wn.w;
    }

    float gr = 0.f, gz = 0.f, gn = 0.f;
    if (gi_mat) {
        const float* gm = gi_mat + (size_t)b * gi_stride;
        gr = gm[h]; gz = gm[HH + h]; gn = gm[2 * HH + h];
    }
    if (gi_vec) {
        gr += gi_vec[h]; gz += gi_vec[HH + h]; gn += gi_vec[2 * HH + h];
    }
    float hr = ar + bhh[h];
    float hz = az + bhh[HH + h];
    float hn = anh + bhh[2 * HH + h];
    float r = 1.f / (1.f + expf(-(gr + hr)));
    float z = 1.f / (1.f + expf(-(gz + hz)));
    float n = tanhf(gn + anx + r * hn);
    float hp = ht4_in[pt_idx(h, b)];
    float out = (1.f - z) * n + z * hp;
    ht4_out[pt_idx(h, b)] = out;
    if (cat_out) cat_out[(size_t)b * H2 + h] = out;
}

// ---------------- attention (one block per batch b) ----------------
// d1 in packed-transposed layout. Writes ctx transposed-packed + cat row (+H).
__global__ void __launch_bounds__(256)
attn_kernel(const float* __restrict__ proj,
            const float* __restrict__ encout,
            const float* __restrict__ d1t4,
            const int* __restrict__ src_ids,
            float* __restrict__ ctxt4,
            float* __restrict__ catrow) {
    int b = blockIdx.x;
    __shared__ float sc[SS];
    int tid = threadIdx.x;
    int lane = tid & 31;
    int warp = tid >> 5;

    for (int s = warp; s < SS; s += 8) {
        const float* pr = proj + ((size_t)b * SS + s) * HH;
        float p = 0.f;
#pragma unroll
        for (int j = 0; j < 8; j++) {
            int k0 = j * 128 + lane * 4;
            float4 dv = *reinterpret_cast<const float4*>(d1t4 + (size_t)((k0 >> 2) * 128 + b * 4));
            float4 pv = *reinterpret_cast<const float4*>(pr + k0);
            p += dv.x * pv.x + dv.y * pv.y + dv.z * pv.z + dv.w * pv.w;
        }
#pragma unroll
        for (int o = 16; o; o >>= 1) p += __shfl_xor_sync(0xffffffffu, p, o);
        if (lane == 0) sc[s] = (src_ids[b * SS + s] != 0) ? p : -1e9f;
    }
    __syncthreads();
    if (warp == 0) {
        float v0 = sc[lane], v1 = sc[lane + 32];
        float m = fmaxf(v0, v1);
#pragma unroll
        for (int o = 16; o; o >>= 1) m = fmaxf(m, __shfl_xor_sync(0xffffffffu, m, o));
        float e0 = expf(v0 - m), e1 = expf(v1 - m);
        float su = e0 + e1;
#pragma unroll
        for (int o = 16; o; o >>= 1) su += __shfl_xor_sync(0xffffffffu, su, o);
        sc[lane] = e0 / su;
        sc[lane + 32] = e1 / su;
    }
    __syncthreads();
    for (int h = tid; h < HH; h += 256) {
        const float* eb = encout + (size_t)b * SS * HH + h;
        float a = 0.f;
#pragma unroll 8
        for (int s = 0; s < SS; s++) a += sc[s] * eb[(size_t)s * HH];
        ctxt4[pt_idx(h, b)] = a;
        catrow[(size_t)b * H2 + HH + h] = a;
    }
}

// ---------------- host launcher ----------------
extern "C" void kernel_launch(void* const* d_in, const int* in_sizes, int n_in,
                              void* d_out, int out_size) {
    const int*   src_ids  = (const int*)d_in[0];
    const int*   tgt_ids  = (const int*)d_in[2];
    const float* enc_emb  = (const float*)d_in[3];
    const float* dec_emb  = (const float*)d_in[4];
    const float* enc_wih0 = (const float*)d_in[5];
    const float* enc_whh0 = (const float*)d_in[6];
    const float* enc_bih0 = (const float*)d_in[7];
    const float* enc_bhh0 = (const float*)d_in[8];
    const float* enc_wih1 = (const float*)d_in[9];
    const float* enc_whh1 = (const float*)d_in[10];
    const float* enc_bih1 = (const float*)d_in[11];
    const float* enc_bhh1 = (const float*)d_in[12];
    const float* dec_wih0 = (const float*)d_in[13];
    const float* dec_whh0 = (const float*)d_in[14];
    const float* dec_bih0 = (const float*)d_in[15];
    const float* dec_bhh0 = (const float*)d_in[16];
    const float* dec_wih1 = (const float*)d_in[17];
    const float* dec_whh1 = (const float*)d_in[18];
    const float* dec_bih1 = (const float*)d_in[19];
    const float* dec_bhh1 = (const float*)d_in[20];
    const float* attn_w   = (const float*)d_in[21];
    const float* out_w    = (const float*)d_in[22];
    const float* out_b    = (const float*)d_in[23];
    float* out = (float*)d_out;

    float* base = nullptr;
    cudaGetSymbolAddress((void**)&base, g_scratch);
    float* embS   = base + OFF_EMBS;
    float* gi0    = base + OFF_GI0;
    float* h0seq  = base + OFF_H0SEQ;
    float* gi1    = base + OFF_GI1;
    float* encout = base + OFF_ENCOUT;
    float* proj   = base + OFF_PROJ;
    float* embT   = base + OFF_EMBT;
    float* epre   = base + OFF_EPRE;
    float* cat    = base + OFF_CAT;
    float* h0A    = base + OFF_H0A;
    float* h0B    = base + OFF_H0B;
    float* h1A    = base + OFF_H1A;
    float* h1B    = base + OFF_H1B;
    float* ctxt4  = base + OFF_CTXT;

    // ---- encoder ----
    embed_enc_kernel<<<(BB * SS * EE + 255) / 256, 256>>>(src_ids, enc_emb, embS);
    gemm128_kernel<false><<<dim3(H3 / 128, (BB * SS) / 128), 256>>>(
        embS, EE, enc_wih0, EE, enc_bih0, gi0, BB * SS, H3, EE);
    // zero both initial states (h0A, h1A are adjacent except h0B between -> zero all 4)
    zero_kernel<<<(4 * BB * HH + 255) / 256, 256>>>(h0A, 4 * BB * HH);

    float* h0_cur = h0A; float* h0_nxt = h0B;
    float* h1_cur = h1A; float* h1_nxt = h1B;

    // layer-0 scan
    for (int t = 0; t < SS; t++) {
        gru_enc_step<<<128, 256>>>(gi0 + (size_t)t * H3, SS * H3, enc_whh0, enc_bhh0,
                                   h0_cur, h0_nxt, h0seq + (size_t)t * HH, SS * HH);
        float* tmp = h0_cur; h0_cur = h0_nxt; h0_nxt = tmp;
    }
    gemm128_kernel<false><<<dim3(H3 / 128, (BB * SS) / 128), 256>>>(
        h0seq, HH, enc_wih1, HH, enc_bih1, gi1, BB * SS, H3, HH);
    // layer-1 scan
    for (int t = 0; t < SS; t++) {
        gru_enc_step<<<128, 256>>>(gi1 + (size_t)t * H3, SS * H3, enc_whh1, enc_bhh1,
                                   h1_cur, h1_nxt, encout + (size_t)t * HH, SS * HH);
        float* tmp = h1_cur; h1_cur = h1_nxt; h1_nxt = tmp;
    }
    // proj = encout @ attn_w^T
    gemm128_kernel<false><<<dim3(HH / 128, (BB * SS) / 128), 256>>>(
        encout, HH, attn_w, HH, nullptr, proj, BB * SS, HH, HH);

    // ---- decoder pre ----
    embed_dec_kernel<<<(TM * BB * EE + 255) / 256, 256>>>(tgt_ids, dec_emb, embT);
    gemm128_kernel<false><<<dim3(H3 / 128, (TM * BB + 127) / 128), 256>>>(
        embT, EE, dec_wih0, EE + HH, dec_bih0, epre, TM * BB, H3, EE);

    // ---- decoder loop ----
    for (int t = 0; t < TM; t++) {
        float* epre_t = epre + (size_t)t * BB * H3;
        float* cat_t  = cat + (size_t)t * BB * H2;
        attn_kernel<<<BB, 256>>>(proj, encout, h1_cur, src_ids, ctxt4, cat_t);
        // layer 0: i-side = epre + ctx @ dec_wih0[:, E:]^T ; h-side = h0 @ dec_whh0^T
        gru_dec_step<<<128, 256>>>(epre_t, H3, nullptr,
                                   ctxt4, dec_wih0, EE + HH, EE,
                                   h0_cur, dec_whh0, dec_bhh0,
                                   h0_nxt, nullptr);
        // layer 1: i-side = bih1 + h0_new @ dec_wih1^T ; h-side = h1 @ dec_whh1^T
        gru_dec_step<<<128, 256>>>(nullptr, 0, dec_bih1,
                                   h0_nxt, dec_wih1, HH, 0,
                                   h1_cur, dec_whh1, dec_bhh1,
                                   h1_nxt, cat_t);
        float* tmp;
        tmp = h0_cur; h0_cur = h0_nxt; h0_nxt = tmp;
        tmp = h1_cur; h1_cur = h1_nxt; h1_nxt = tmp;
    }

    // ---- final projection: logits = cat @ out_w^T + out_b, permuted to (B, TM, V) ----
    gemm128_kernel<true><<<dim3(VV / 128, (TM * BB + 127) / 128), 256>>>(
        cat, H2, out_w, H2, out_b, out, TM * BB, VV, H2);
}

// round 4
// speedup vs baseline: 3.1674x; 2.8426x over previous
#include <cuda_runtime.h>
#include <cstdint>
#include <cstdio>

// Problem dims
#define BB 32
#define SS 64
#define TT 48
#define TM 47      // T-1 decoder steps
#define VV 32000
#define EE 512
#define HH 1024
#define H3 3072
#define H2 2048
#define KSPLIT 4
#define PARTSZ ((size_t)BB * H3)

// ---------------- scratch (device global, no allocs) ----------------
#define OFF_EMBS   0ull                                   // B*S*E
#define OFF_GI0    (OFF_EMBS   + (size_t)BB*SS*EE)        // [t][n][b] slabs
#define OFF_H0SEQ  (OFF_GI0    + (size_t)BB*SS*H3)        // row-major [b][t][h]
#define OFF_GI1    (OFF_H0SEQ  + (size_t)BB*SS*HH)
#define OFF_ENCOUT (OFF_GI1    + (size_t)BB*SS*H3)        // row-major [b][t][h]
#define OFF_PROJ   (OFF_ENCOUT + (size_t)BB*SS*HH)        // row-major
#define OFF_EMBT   (OFF_PROJ   + (size_t)BB*SS*HH)        // rows m=t*B+b
#define OFF_EPRE   (OFF_EMBT   + (size_t)TM*BB*EE)        // [t][n][b] slabs
#define OFF_CAT    (OFF_EPRE   + (size_t)TM*BB*H3)        // rows m=t*B+b, [d1|ctx]
#define OFF_H0A    (OFF_CAT    + (size_t)TM*BB*H2)        // state [k][b]
#define OFF_H0B    (OFF_H0A    + (size_t)BB*HH)
#define OFF_H1A    (OFF_H0B    + (size_t)BB*HH)
#define OFF_H1B    (OFF_H1A    + (size_t)BB*HH)
#define OFF_CTXT   (OFF_H1B    + (size_t)BB*HH)           // ctx [k][b]
#define OFF_D1ROW  (OFF_CTXT   + (size_t)BB*HH)           // d1 row-major [b][h]
#define OFF_PART   (OFF_D1ROW  + (size_t)BB*HH)           // 8 partials [n][b]
#define OFF_WT     (OFF_PART   + 8*PARTSZ)                // 6 transposed weights [k][n]
#define WT_SZ      ((size_t)HH * H3)
#define SCRATCH_TOTAL (OFF_WT + 6*WT_SZ)

__device__ float g_scratch[SCRATCH_TOTAL];

// ---------------- misc ----------------
__global__ void zero_kernel(float* p, int n) {
    int i = blockIdx.x * blockDim.x + threadIdx.x;
    if (i < n) p[i] = 0.f;
}

__global__ void embed_enc_kernel(const int* __restrict__ ids,
                                 const float* __restrict__ table,
                                 float* __restrict__ out) {
    int i = blockIdx.x * blockDim.x + threadIdx.x;
    if (i >= BB * SS * EE) return;
    int tok = i / EE;
    int e = i % EE;
    out[i] = table[(size_t)ids[tok] * EE + e];
}

// decoder embedding rows m = t*B + b
__global__ void embed_dec_kernel(const int* __restrict__ tgt,
                                 const float* __restrict__ table,
                                 float* __restrict__ out) {
    int i = blockIdx.x * blockDim.x + threadIdx.x;
    if (i >= TM * BB * EE) return;
    int m = i / EE;
    int e = i % EE;
    int t = m / BB;
    int b = m % BB;
    out[i] = table[(size_t)tgt[b * TT + t] * EE + e];
}

// weight transpose: Wt[k][n] = W[n][koff + k], W row stride ldw. grid (H3/32, HH/32), 256 thr
__global__ void transpose_w(const float* __restrict__ W, int ldw, int koff,
                            float* __restrict__ Wt) {
    __shared__ float s[32][33];
    int n0 = blockIdx.x * 32, k0 = blockIdx.y * 32;
    int tx = threadIdx.x & 31, ty = threadIdx.x >> 5;
#pragma unroll
    for (int i = 0; i < 4; i++)
        s[ty + i * 8][tx] = W[(size_t)(n0 + ty + i * 8) * ldw + koff + k0 + tx];
    __syncthreads();
#pragma unroll
    for (int i = 0; i < 4; i++)
        Wt[(size_t)(k0 + ty + i * 8) * H3 + n0 + tx] = s[tx][ty + i * 8];
}

// ---------------- tf32 tensor-core GEMM ----------------
// C[m,n] = sum_k A[m,k] * W[n,k] (+ bias[n]); 128x128 block tile, KC=32.
__device__ __forceinline__ uint32_t f2tf(float f) {
    uint32_t u;
    asm("cvt.rna.tf32.f32 %0, %1;" : "=r"(u) : "f"(f));
    return u;
}

#define MODE_NORM 0
#define MODE_PERM 1   // m = t*32+b -> out row b*TM + t   (final logits)
#define MODE_TENC 2   // m = b*64+t -> [t][n][b] slabs (stride H3*32)
#define MODE_TDEC 3   // m = t*32+b -> [t][n][b] slabs

template <int MODE>
__global__ void __launch_bounds__(256)
gemm_tf32(const float* __restrict__ A, int lda,
          const float* __restrict__ W, int ldw,
          const float* __restrict__ bias,
          float* __restrict__ C, int M, int N, int K) {
    __shared__ uint32_t As[32][132];   // [k][m]
    __shared__ uint32_t Ws[32][132];   // [k][n]
    const int bm = blockIdx.y * 128, bn = blockIdx.x * 128;
    const int tid = threadIdx.x;
    const int warp = tid >> 5, lane = tid & 31;
    const int wm = (warp & 1) * 64, wn = (warp >> 1) * 32;
    const int g = lane >> 2, tig = lane & 3;

    float acc[4][4][4];
#pragma unroll
    for (int a = 0; a < 4; a++)
#pragma unroll
        for (int b = 0; b < 4; b++)
#pragma unroll
            for (int c = 0; c < 4; c++) acc[a][b][c] = 0.f;

    float4 pa[4], pw[4];

    // prefetch chunk 0
#pragma unroll
    for (int i = 0; i < 4; i++) {
        int e = tid + i * 256;
        int m = e >> 3, kq = (e & 7) * 4;
        float4 v = make_float4(0.f, 0.f, 0.f, 0.f);
        if (bm + m < M) v = *reinterpret_cast<const float4*>(A + (size_t)(bm + m) * lda + kq);
        pa[i] = v;
        pw[i] = *reinterpret_cast<const float4*>(W + (size_t)(bn + m) * ldw + kq);
    }
#pragma unroll
    for (int i = 0; i < 4; i++) {
        int e = tid + i * 256;
        int m = e >> 3, kq = (e & 7) * 4;
        As[kq + 0][m] = f2tf(pa[i].x); As[kq + 1][m] = f2tf(pa[i].y);
        As[kq + 2][m] = f2tf(pa[i].z); As[kq + 3][m] = f2tf(pa[i].w);
        Ws[kq + 0][m] = f2tf(pw[i].x); Ws[kq + 1][m] = f2tf(pw[i].y);
        Ws[kq + 2][m] = f2tf(pw[i].z); Ws[kq + 3][m] = f2tf(pw[i].w);
    }
    __syncthreads();

    for (int k0 = 0; k0 < K; k0 += 32) {
        bool has_next = (k0 + 32) < K;
        if (has_next) {
#pragma unroll
            for (int i = 0; i < 4; i++) {
                int e = tid + i * 256;
                int m = e >> 3, kq = (e & 7) * 4;
                float4 v = make_float4(0.f, 0.f, 0.f, 0.f);
                if (bm + m < M)
                    v = *reinterpret_cast<const float4*>(A + (size_t)(bm + m) * lda + k0 + 32 + kq);
                pa[i] = v;
                pw[i] = *reinterpret_cast<const float4*>(W + (size_t)(bn + m) * ldw + k0 + 32 + kq);
            }
        }
#pragma unroll
        for (int kk = 0; kk < 32; kk += 8) {
            uint32_t af[4][4];
#pragma unroll
            for (int mt = 0; mt < 4; mt++) {
                int ml = wm + mt * 16 + g;
                af[mt][0] = As[kk + tig][ml];
                af[mt][1] = As[kk + tig][ml + 8];
                af[mt][2] = As[kk + tig + 4][ml];
                af[mt][3] = As[kk + tig + 4][ml + 8];
            }
            uint32_t bf[4][2];
#pragma unroll
            for (int nt = 0; nt < 4; nt++) {
                int nl = wn + nt * 8 + g;
                bf[nt][0] = Ws[kk + tig][nl];
                bf[nt][1] = Ws[kk + tig + 4][nl];
            }
#pragma unroll
            for (int mt = 0; mt < 4; mt++)
#pragma unroll
                for (int nt = 0; nt < 4; nt++) {
                    asm volatile(
                        "mma.sync.aligned.m16n8k8.row.col.f32.tf32.tf32.f32 "
                        "{%0,%1,%2,%3}, {%4,%5,%6,%7}, {%8,%9}, {%0,%1,%2,%3};\n"
                        : "+f"(acc[mt][nt][0]), "+f"(acc[mt][nt][1]),
                          "+f"(acc[mt][nt][2]), "+f"(acc[mt][nt][3])
                        : "r"(af[mt][0]), "r"(af[mt][1]), "r"(af[mt][2]), "r"(af[mt][3]),
                          "r"(bf[nt][0]), "r"(bf[nt][1]));
                }
        }
        __syncthreads();
        if (has_next) {
#pragma unroll
            for (int i = 0; i < 4; i++) {
                int e = tid + i * 256;
                int m = e >> 3, kq = (e & 7) * 4;
                As[kq + 0][m] = f2tf(pa[i].x); As[kq + 1][m] = f2tf(pa[i].y);
                As[kq + 2][m] = f2tf(pa[i].z); As[kq + 3][m] = f2tf(pa[i].w);
                Ws[kq + 0][m] = f2tf(pw[i].x); Ws[kq + 1][m] = f2tf(pw[i].y);
                Ws[kq + 2][m] = f2tf(pw[i].z); Ws[kq + 3][m] = f2tf(pw[i].w);
            }
            __syncthreads();
        }
    }

    // epilogue
#pragma unroll
    for (int mt = 0; mt < 4; mt++) {
#pragma unroll
        for (int i2 = 0; i2 < 2; i2++) {
            int m = bm + wm + mt * 16 + g + i2 * 8;
            if (m >= M) continue;
#pragma unroll
            for (int nt = 0; nt < 4; nt++) {
#pragma unroll
                for (int j = 0; j < 2; j++) {
                    int n = bn + wn + nt * 8 + tig * 2 + j;
                    float v = acc[mt][nt][i2 * 2 + j];
                    if (bias) v += bias[n];
                    if (MODE == MODE_NORM) {
                        C[(size_t)m * N + n] = v;
                    } else if (MODE == MODE_PERM) {
                        int b = m & 31, t = m >> 5;
                        C[(size_t)(b * TM + t) * N + n] = v;
                    } else if (MODE == MODE_TENC) {
                        int t = m & 63, b = m >> 6;
                        C[((size_t)t * H3 + n) * 32 + b] = v;
                    } else {  // MODE_TDEC
                        int t = m >> 5, b = m & 31;
                        C[((size_t)t * H3 + n) * 32 + b] = v;
                    }
                }
            }
        }
    }
}

// ---------------- recurrent small GEMM: partial[b][n] over a K-split ----------------
// A in [k][b] (k-major, stride 32), Wt in [k][n] (stride H3).
// grid (H3/64, KSPLIT, nmat). Writes part[(z*KSPLIT+y)] in [n][b] layout.
__global__ void __launch_bounds__(256)
rec_gemm(const float* __restrict__ A0, const float* __restrict__ W0,
         const float* __restrict__ A1, const float* __restrict__ W1,
         float* __restrict__ part) {
    const float* At = blockIdx.z ? A1 : A0;
    const float* Wt = blockIdx.z ? W1 : W0;
    __shared__ float sA[256 * 32];
    const int n0 = blockIdx.x * 64;
    const int k0 = blockIdx.y * (HH / KSPLIT);   // 256 k per split
    const int tid = threadIdx.x;

    const float4* src = reinterpret_cast<const float4*>(At + (size_t)k0 * 32);
#pragma unroll
    for (int i = 0; i < 8; i++)
        reinterpret_cast<float4*>(sA)[tid + i * 256] = src[tid + i * 256];
    __syncthreads();

    const int nq = (tid & 15) * 4;
    const int b0 = (tid >> 4) * 2;
    float4 acc0 = make_float4(0.f, 0.f, 0.f, 0.f);
    float4 acc1 = make_float4(0.f, 0.f, 0.f, 0.f);
    const float* wp = Wt + (size_t)k0 * H3 + n0 + nq;
#pragma unroll 4
    for (int k = 0; k < HH / KSPLIT; k++) {
        float4 w = *reinterpret_cast<const float4*>(wp + (size_t)k * H3);
        float a0 = sA[k * 32 + b0];
        float a1 = sA[k * 32 + b0 + 1];
        acc0.x += a0 * w.x; acc0.y += a0 * w.y; acc0.z += a0 * w.z; acc0.w += a0 * w.w;
        acc1.x += a1 * w.x; acc1.y += a1 * w.y; acc1.z += a1 * w.z; acc1.w += a1 * w.w;
    }
    float* P = part + (size_t)(blockIdx.z * KSPLIT + blockIdx.y) * PARTSZ;
    P[(size_t)(n0 + nq + 0) * 32 + b0] = acc0.x;
    P[(size_t)(n0 + nq + 1) * 32 + b0] = acc0.y;
    P[(size_t)(n0 + nq + 2) * 32 + b0] = acc0.z;
    P[(size_t)(n0 + nq + 3) * 32 + b0] = acc0.w;
    P[(size_t)(n0 + nq + 0) * 32 + b0 + 1] = acc1.x;
    P[(size_t)(n0 + nq + 1) * 32 + b0 + 1] = acc1.y;
    P[(size_t)(n0 + nq + 2) * 32 + b0 + 1] = acc1.z;
    P[(size_t)(n0 + nq + 3) * 32 + b0 + 1] = acc1.w;
}

// ---------------- GRU gate: sum partials, apply nonlinearity, fan out state ----------------
__global__ void __launch_bounds__(256)
gru_gate(const float* __restrict__ partH,
         const float* __restrict__ partX,       // nullable
         const float* __restrict__ gi_slab,     // nullable [n][b] slab
         const float* __restrict__ gi_vec,      // nullable (bih)
         const float* __restrict__ bhh,
         const float* __restrict__ h_in,        // [k][b]
         float* __restrict__ h_out,             // [k][b]
         float* __restrict__ seq_row, int seq_stride,  // nullable, [b*stride + h]
         float* __restrict__ cat_row,           // nullable, + b*H2 + h
         float* __restrict__ d1row)             // nullable, [b*H + h]
{
    int idx = blockIdx.x * 256 + threadIdx.x;
    int b = idx & 31, h = idx >> 5;
    float gr = 0.f, gz = 0.f, gn = 0.f;
    if (gi_slab) {
        gr = gi_slab[(size_t)h * 32 + b];
        gz = gi_slab[(size_t)(HH + h) * 32 + b];
        gn = gi_slab[(size_t)(2 * HH + h) * 32 + b];
    }
    if (gi_vec) { gr += gi_vec[h]; gz += gi_vec[HH + h]; gn += gi_vec[2 * HH + h]; }
    float hr = bhh[h], hz = bhh[HH + h], hn = bhh[2 * HH + h];
#pragma unroll
    for (int j = 0; j < KSPLIT; j++) {
        const float* P = partH + (size_t)j * PARTSZ;
        hr += P[(size_t)h * 32 + b];
        hz += P[(size_t)(HH + h) * 32 + b];
        hn += P[(size_t)(2 * HH + h) * 32 + b];
    }
    if (partX) {
#pragma unroll
        for (int j = 0; j < KSPLIT; j++) {
            const float* P = partX + (size_t)j * PARTSZ;
            gr += P[(size_t)h * 32 + b];
            gz += P[(size_t)(HH + h) * 32 + b];
            gn += P[(size_t)(2 * HH + h) * 32 + b];
        }
    }
    float r = 1.f / (1.f + expf(-(gr + hr)));
    float z = 1.f / (1.f + expf(-(gz + hz)));
    float n = tanhf(gn + r * hn);
    float hp = h_in[(size_t)h * 32 + b];
    float out = (1.f - z) * n + z * hp;
    h_out[(size_t)h * 32 + b] = out;
    if (seq_row) seq_row[(size_t)b * seq_stride + h] = out;
    if (cat_row) cat_row[(size_t)b * H2 + h] = out;
    if (d1row) d1row[(size_t)b * HH + h] = out;
}

// ---------------- attention ----------------
__global__ void __launch_bounds__(256)
attn_kernel(const float* __restrict__ proj,
            const float* __restrict__ encout,
            const float* __restrict__ d1row,
            const int* __restrict__ src_ids,
            float* __restrict__ ctxt,           // [k][b]
            float* __restrict__ catrow) {       // + b*H2 + HH + h
    int b = blockIdx.x;
    __shared__ float sc[SS];
    int tid = threadIdx.x;
    int lane = tid & 31;
    int warp = tid >> 5;
    const float* d1b = d1row + (size_t)b * HH;

    for (int s = warp; s < SS; s += 8) {
        const float* pr = proj + ((size_t)b * SS + s) * HH;
        float p = 0.f;
#pragma unroll
        for (int j = 0; j < 8; j++) {
            int k0 = j * 128 + lane * 4;
            float4 dv = *reinterpret_cast<const float4*>(d1b + k0);
            float4 pv = *reinterpret_cast<const float4*>(pr + k0);
            p += dv.x * pv.x + dv.y * pv.y + dv.z * pv.z + dv.w * pv.w;
        }
#pragma unroll
        for (int o = 16; o; o >>= 1) p += __shfl_xor_sync(0xffffffffu, p, o);
        if (lane == 0) sc[s] = (src_ids[b * SS + s] != 0) ? p : -1e9f;
    }
    __syncthreads();
    if (warp == 0) {
        float v0 = sc[lane], v1 = sc[lane + 32];
        float m = fmaxf(v0, v1);
#pragma unroll
        for (int o = 16; o; o >>= 1) m = fmaxf(m, __shfl_xor_sync(0xffffffffu, m, o));
        float e0 = expf(v0 - m), e1 = expf(v1 - m);
        float su = e0 + e1;
#pragma unroll
        for (int o = 16; o; o >>= 1) su += __shfl_xor_sync(0xffffffffu, su, o);
        sc[lane] = e0 / su;
        sc[lane + 32] = e1 / su;
    }
    __syncthreads();
    for (int h = tid; h < HH; h += 256) {
        const float* eb = encout + (size_t)b * SS * HH + h;
        float a = 0.f;
#pragma unroll 8
        for (int s = 0; s < SS; s++) a += sc[s] * eb[(size_t)s * HH];
        ctxt[(size_t)h * 32 + b] = a;
        catrow[(size_t)b * H2 + HH + h] = a;
    }
}

// ---------------- host launcher ----------------
extern "C" void kernel_launch(void* const* d_in, const int* in_sizes, int n_in,
                              void* d_out, int out_size) {
    const int*   src_ids  = (const int*)d_in[0];
    const int*   tgt_ids  = (const int*)d_in[2];
    const float* enc_emb  = (const float*)d_in[3];
    const float* dec_emb  = (const float*)d_in[4];
    const float* enc_wih0 = (const float*)d_in[5];
    const float* enc_whh0 = (const float*)d_in[6];
    const float* enc_bih0 = (const float*)d_in[7];
    const float* enc_bhh0 = (const float*)d_in[8];
    const float* enc_wih1 = (const float*)d_in[9];
    const float* enc_whh1 = (const float*)d_in[10];
    const float* enc_bih1 = (const float*)d_in[11];
    const float* enc_bhh1 = (const float*)d_in[12];
    const float* dec_wih0 = (const float*)d_in[13];
    const float* dec_whh0 = (const float*)d_in[14];
    const float* dec_bih0 = (const float*)d_in[15];
    const float* dec_bhh0 = (const float*)d_in[16];
    const float* dec_wih1 = (const float*)d_in[17];
    const float* dec_whh1 = (const float*)d_in[18];
    const float* dec_bih1 = (const float*)d_in[19];
    const float* dec_bhh1 = (const float*)d_in[20];
    const float* attn_w   = (const float*)d_in[21];
    const float* out_w    = (const float*)d_in[22];
    const float* out_b    = (const float*)d_in[23];
    float* out = (float*)d_out;

    float* base = nullptr;
    cudaGetSymbolAddress((void**)&base, g_scratch);
    float* embS   = base + OFF_EMBS;
    float* gi0    = base + OFF_GI0;
    float* h0seq  = base + OFF_H0SEQ;
    float* gi1    = base + OFF_GI1;
    float* encout = base + OFF_ENCOUT;
    float* proj   = base + OFF_PROJ;
    float* embT   = base + OFF_EMBT;
    float* epre   = base + OFF_EPRE;
    float* cat    = base + OFF_CAT;
    float* h0A    = base + OFF_H0A;
    float* h0B    = base + OFF_H0B;
    float* h1A    = base + OFF_H1A;
    float* h1B    = base + OFF_H1B;
    float* ctxt   = base + OFF_CTXT;
    float* d1row  = base + OFF_D1ROW;
    float* part   = base + OFF_PART;
    float* wt_ewhh0 = base + OFF_WT + 0 * WT_SZ;
    float* wt_ewhh1 = base + OFF_WT + 1 * WT_SZ;
    float* wt_dwhh0 = base + OFF_WT + 2 * WT_SZ;
    float* wt_dwhh1 = base + OFF_WT + 3 * WT_SZ;
    float* wt_dwih0c = base + OFF_WT + 4 * WT_SZ;  // dec_wih0[:, E:]
    float* wt_dwih1 = base + OFF_WT + 5 * WT_SZ;

    dim3 tgrid(H3 / 32, HH / 32);
    transpose_w<<<tgrid, 256>>>(enc_whh0, HH, 0, wt_ewhh0);
    transpose_w<<<tgrid, 256>>>(enc_whh1, HH, 0, wt_ewhh1);
    transpose_w<<<tgrid, 256>>>(dec_whh0, HH, 0, wt_dwhh0);
    transpose_w<<<tgrid, 256>>>(dec_whh1, HH, 0, wt_dwhh1);
    transpose_w<<<tgrid, 256>>>(dec_wih0, EE + HH, EE, wt_dwih0c);
    transpose_w<<<tgrid, 256>>>(dec_wih1, HH, 0, wt_dwih1);

    // ---- encoder ----
    embed_enc_kernel<<<(BB * SS * EE + 255) / 256, 256>>>(src_ids, enc_emb, embS);
    gemm_tf32<MODE_TENC><<<dim3(H3 / 128, 16), 256>>>(
        embS, EE, enc_wih0, EE, enc_bih0, gi0, BB * SS, H3, EE);
    zero_kernel<<<(4 * BB * HH + 255) / 256, 256>>>(h0A, 4 * BB * HH);

    float* h0_cur = h0A; float* h0_nxt = h0B;
    float* h1_cur = h1A; float* h1_nxt = h1B;

    // layer-0 scan
    for (int t = 0; t < SS; t++) {
        rec_gemm<<<dim3(H3 / 64, KSPLIT, 1), 256>>>(h0_cur, wt_ewhh0, nullptr, nullptr, part);
        gru_gate<<<BB * HH / 256, 256>>>(part, nullptr,
                                         gi0 + (size_t)t * H3 * 32, nullptr, enc_bhh0,
                                         h0_cur, h0_nxt,
                                         h0seq + (size_t)t * HH, SS * HH, nullptr, nullptr);
        float* tmp = h0_cur; h0_cur = h0_nxt; h0_nxt = tmp;
    }
    gemm_tf32<MODE_TENC><<<dim3(H3 / 128, 16), 256>>>(
        h0seq, HH, enc_wih1, HH, enc_bih1, gi1, BB * SS, H3, HH);
    // layer-1 scan
    for (int t = 0; t < SS; t++) {
        rec_gemm<<<dim3(H3 / 64, KSPLIT, 1), 256>>>(h1_cur, wt_ewhh1, nullptr, nullptr, part);
        gru_gate<<<BB * HH / 256, 256>>>(part, nullptr,
                                         gi1 + (size_t)t * H3 * 32, nullptr, enc_bhh1,
                                         h1_cur, h1_nxt,
                                         encout + (size_t)t * HH, SS * HH, nullptr,
                                         (t == SS - 1) ? d1row : nullptr);
        float* tmp = h1_cur; h1_cur = h1_nxt; h1_nxt = tmp;
    }
    // proj = encout @ attn_w^T
    gemm_tf32<MODE_NORM><<<dim3(HH / 128, 16), 256>>>(
        encout, HH, attn_w, HH, nullptr, proj, BB * SS, HH, HH);

    // ---- decoder pre ----
    embed_dec_kernel<<<(TM * BB * EE + 255) / 256, 256>>>(tgt_ids, dec_emb, embT);
    gemm_tf32<MODE_TDEC><<<dim3(H3 / 128, (TM * BB + 127) / 128), 256>>>(
        embT, EE, dec_wih0, EE + HH, dec_bih0, epre, TM * BB, H3, EE);

    // ---- decoder loop ----
    for (int t = 0; t < TM; t++) {
        float* epre_t = epre + (size_t)t * H3 * 32;
        float* cat_t  = cat + (size_t)t * BB * H2;
        attn_kernel<<<BB, 256>>>(proj, encout, d1row, src_ids, ctxt, cat_t);
        // layer 0: h-side (z=0) = h0 @ whh0^T ; x-side (z=1) = ctx @ wih0[:,E:]^T
        rec_gemm<<<dim3(H3 / 64, KSPLIT, 2), 256>>>(h0_cur, wt_dwhh0, ctxt, wt_dwih0c, part);
        gru_gate<<<BB * HH / 256, 256>>>(part, part + 4 * PARTSZ,
                                         epre_t, nullptr, dec_bhh0,
                                         h0_cur, h0_nxt, nullptr, 0, nullptr, nullptr);
        // layer 1: h-side = h1 @ whh1^T ; x-side = h0_new @ wih1^T
        rec_gemm<<<dim3(H3 / 64, KSPLIT, 2), 256>>>(h1_cur, wt_dwhh1, h0_nxt, wt_dwih1, part);
        gru_gate<<<BB * HH / 256, 256>>>(part, part + 4 * PARTSZ,
                                         nullptr, dec_bih1, dec_bhh1,
                                         h1_cur, h1_nxt, nullptr, 0, cat_t, d1row);
        float* tmp;
        tmp = h0_cur; h0_cur = h0_nxt; h0_nxt = tmp;
        tmp = h1_cur; h1_cur = h1_nxt; h1_nxt = tmp;
    }

    // ---- final projection ----
    gemm_tf32<MODE_PERM><<<dim3(VV / 128, (TM * BB + 127) / 128), 256>>>(
        cat, H2, out_w, H2, out_b, out, TM * BB, VV, H2);
}